// round 14
// baseline (speedup 1.0000x reference)
#include <cuda_runtime.h>
#include <cstdint>

#define Bb 2
#define Nn 2048
#define Ff 128
#define Hh 4
#define HC 256
#define MI 128
#define SPLIT 4
#define JR (Nn/SPLIT)
#define NT (JR/64)
#define NCTA ((Bb*Nn/MI)*SPLIT)  // 128
#define GEMM_BLKS 128
#define MASK_BLKS 20

// kernel-B smem: double-buffered {B-image 34816, eb 2048, masks 1024}
#define KB_STG   37888
#define KB_B(st) ((st)*KB_STG)
#define KB_E(st) (34816 + (st)*KB_STG)
#define KB_M(st) (36864 + (st)*KB_STG)
#define KB_TOT   (2*KB_STG)

// precompute smem (32 nodes/CTA)
#define SMP_XS     0
#define SMP_WS(st) (16384 + (st)*32768)
#define SMP_RS     81920
#define SMP_RD     82432
#define SMP_TOT    82944
#define SMP_TR     16384

typedef unsigned long long u64;

__device__ unsigned g_hB [Bb*32*8704];     // f16x2 fragment image per 64-j tile
__device__ uint2    g_mask[Bb*32*Nn];      // per (b, jt, i): (even-j ballot, odd-j ballot)
__device__ float2   g_sE [Bb*Nn*Hh];
__device__ float2   g_dE [Bb*Nn*Hh];
__device__ float    g_part[(size_t)NCTA*MI*HC];
__device__ float    g_lsum[NCTA*MI*Hh];

#define ONES_H2 0x3C003C00u

__device__ __forceinline__ unsigned pack_h2(float lo, float hi) {
    unsigned r; asm("cvt.rn.f16x2.f32 %0, %1, %2;" : "=r"(r) : "f"(hi), "f"(lo));
    return r;
}
__device__ __forceinline__ void mma_f16(float* d, unsigned a0, unsigned a1,
                                        unsigned a2, unsigned a3, unsigned b0, unsigned b1) {
    asm volatile("mma.sync.aligned.m16n8k16.row.col.f32.f16.f16.f32 "
        "{%0,%1,%2,%3}, {%4,%5,%6,%7}, {%8,%9}, {%0,%1,%2,%3};"
        : "+f"(d[0]), "+f"(d[1]), "+f"(d[2]), "+f"(d[3])
        : "r"(a0), "r"(a1), "r"(a2), "r"(a3), "r"(b0), "r"(b1));
}
__device__ __forceinline__ float pmax2p(u64 a, u64 b) {
    u64 dv; float lo, hi;
    asm("mul.rn.f32x2 %0, %1, %2;" : "=l"(dv) : "l"(a), "l"(b));
    asm("mov.b64 {%0, %1}, %2;" : "=f"(lo), "=f"(hi) : "l"(dv));
    return fmaxf(lo, hi);
}
__device__ __forceinline__ uint32_t smem_u32(const void* p) {
    uint32_t a;
    asm("{ .reg .u64 t; cvta.to.shared.u64 t, %1; cvt.u32.u64 %0, t; }" : "=r"(a) : "l"(p));
    return a;
}
__device__ __forceinline__ void cp16(uint32_t dst, const void* src) {
    asm volatile("cp.async.cg.shared.global [%0], [%1], 16;" :: "r"(dst), "l"(src));
}
#define CP_COMMIT() asm volatile("cp.async.commit_group;" ::: "memory")
#define CP_WAIT(n)  asm volatile("cp.async.wait_group %0;" :: "n"(n) : "memory")

// ------- Kernel A: blocks 0..127 = h GEMM (round-10 code); 128..147 = A-mask build -------
__global__ __launch_bounds__(512) void precompute_kernel(
    const float* __restrict__ X, const float* __restrict__ Wg,
    const float* __restrict__ asrc, const float* __restrict__ adst,
    const float* __restrict__ A)
{
    extern __shared__ char smp[];
    const int t = threadIdx.x;

    if (blockIdx.x >= GEMM_BLKS) {
        // ---- mask builder: 131072 rounds, each = one (row, 64-j tile) ----
        const int wid  = (blockIdx.x - GEMM_BLKS)*16 + (t >> 5);  // 0..319
        const int lane = t & 31;
        const long base = (long)wid * 420;                        // 320*420 >= 131072
        float2 f[2][12];
        auto ldb = [&](int bt, int buf) {
#pragma unroll
            for (int k = 0; k < 12; ++k) {
                long rr = base + (long)bt*12 + k; if (rr > 131071) rr = 131071;
                const int bi = (int)(rr >> 5), jt = (int)(rr & 31);
                f[buf][k] = __ldcs((const float2*)(A + (size_t)bi*Nn + jt*64 + lane*2));
            }
        };
        ldb(0, 0);
#pragma unroll 2
        for (int bt = 0; bt < 35; ++bt) {
            const int buf = bt & 1;
            if (bt + 1 < 35) ldb(bt + 1, buf ^ 1);
#pragma unroll
            for (int k = 0; k < 12; ++k) {
                long rr = base + (long)bt*12 + k; if (rr > 131071) rr = 131071;
                const int bi = (int)(rr >> 5), jt = (int)(rr & 31);
                const unsigned bx = __ballot_sync(0xffffffffu, f[buf][k].x != 0.f);
                const unsigned by = __ballot_sync(0xffffffffu, f[buf][k].y != 0.f);
                if (lane == 0)
                    g_mask[(size_t)((bi >> 11)*32 + jt)*Nn + (bi & 2047)] = make_uint2(bx, by);
            }
        }
        return;
    }

    float* xs    = (float*)(smp + SMP_XS);
    float* red_s = (float*)(smp + SMP_RS);
    float* red_d = (float*)(smp + SMP_RD);
    const int bn0 = blockIdx.x * 32;
    const int c4  = t & 63, nq = t >> 6;
    const uint32_t smb = smem_u32(smp);

#pragma unroll
    for (int r = 0; r < 2; ++r) {
        const int u = t + r*512, n = u >> 5, f4 = u & 31;
        *(float4*)&xs[n*Ff + f4*4] = *(const float4*)(X + (size_t)(bn0+n)*Ff + f4*4);
    }
    auto stageW = [&](int fc, int st) {
#pragma unroll
        for (int k = 0; k < 4; ++k) {
            const int u = t + k*512, lf = u >> 6, cq = u & 63;
            cp16(smb + SMP_WS(st) + (lf*256 + cq*4)*4,
                 Wg + (size_t)(cq>>4)*(Ff*64) + (size_t)(fc+lf)*64 + (cq&15)*4);
        }
        CP_COMMIT();
    };

    float acc[4][4];
#pragma unroll
    for (int jj = 0; jj < 4; ++jj)
#pragma unroll
        for (int cc = 0; cc < 4; ++cc) acc[jj][cc] = 0.f;

    stageW(0, 0);
    for (int ch = 0; ch < 4; ++ch) {
        const int st = ch & 1;
        if (ch + 1 < 4) { stageW(32*(ch+1), st ^ 1); CP_WAIT(1); }
        else            { CP_WAIT(0); }
        __syncthreads();
        const float* ws = (const float*)(smp + SMP_WS(st));
#pragma unroll
        for (int lf = 0; lf < 32; ++lf) {
            const float4 w4 = *(const float4*)&ws[lf*256 + 4*c4];
            const float x0 = xs[(4*nq+0)*Ff + 32*ch + lf];
            const float x1 = xs[(4*nq+1)*Ff + 32*ch + lf];
            const float x2 = xs[(4*nq+2)*Ff + 32*ch + lf];
            const float x3 = xs[(4*nq+3)*Ff + 32*ch + lf];
            acc[0][0]=fmaf(x0,w4.x,acc[0][0]); acc[0][1]=fmaf(x0,w4.y,acc[0][1]);
            acc[0][2]=fmaf(x0,w4.z,acc[0][2]); acc[0][3]=fmaf(x0,w4.w,acc[0][3]);
            acc[1][0]=fmaf(x1,w4.x,acc[1][0]); acc[1][1]=fmaf(x1,w4.y,acc[1][1]);
            acc[1][2]=fmaf(x1,w4.z,acc[1][2]); acc[1][3]=fmaf(x1,w4.w,acc[1][3]);
            acc[2][0]=fmaf(x2,w4.x,acc[2][0]); acc[2][1]=fmaf(x2,w4.y,acc[2][1]);
            acc[2][2]=fmaf(x2,w4.z,acc[2][2]); acc[2][3]=fmaf(x2,w4.w,acc[2][3]);
            acc[3][0]=fmaf(x3,w4.x,acc[3][0]); acc[3][1]=fmaf(x3,w4.y,acc[3][1]);
            acc[3][2]=fmaf(x3,w4.z,acc[3][2]); acc[3][3]=fmaf(x3,w4.w,acc[3][3]);
        }
        __syncthreads();
    }

    const float4 as4 = *(const float4*)(asrc + 4*c4);
    const float4 ad4 = *(const float4*)(adst + 4*c4);
#pragma unroll
    for (int jj = 0; jj < 4; ++jj) {
        float ps = acc[jj][0]*as4.x + acc[jj][1]*as4.y + acc[jj][2]*as4.z + acc[jj][3]*as4.w;
        float pd = acc[jj][0]*ad4.x + acc[jj][1]*ad4.y + acc[jj][2]*ad4.z + acc[jj][3]*ad4.w;
#pragma unroll
        for (int o = 1; o < 16; o <<= 1) {
            ps += __shfl_xor_sync(0xffffffffu, ps, o);
            pd += __shfl_xor_sync(0xffffffffu, pd, o);
        }
        if ((t & 15) == 0) {
            red_s[(4*nq+jj)*4 + (c4>>4)] = ps;
            red_d[(4*nq+jj)*4 + (c4>>4)] = pd;
        }
    }
    __syncthreads();

    float* tr = (float*)(smp + SMP_TR);
#pragma unroll
    for (int jj = 0; jj < 4; ++jj)
        *(float4*)&tr[(4*nq+jj)*260 + 4*c4] =
            make_float4(acc[jj][0], acc[jj][1], acc[jj][2], acc[jj][3]);
    if (t < 128) {
        const int n = t >> 2, h = t & 3;
        const float ss = red_s[n*4 + h], sd = red_d[n*4 + h];
        g_sE[(size_t)(bn0+n)*Hh + h] = make_float2(__expf(ss), __expf(0.2f*ss));
        g_dE[(size_t)(bn0+n)*Hh + h] = make_float2(__expf(sd), __expf(0.2f*sd));
    }
    __syncthreads();

    const int b = bn0 >> 11, nl = bn0 & (Nn-1);
    const int T = nl >> 6, sb = (nl & 63) >> 4;
    unsigned* dst = g_hB + (size_t)(b*32 + T)*8704;
#pragma unroll
    for (int k = 0; k < 8; ++k) {
        const int u = t + k*512;
        const int half = u & 1, c = (u >> 1) & 63;
        const int q = (u >> 7) & 3, h = (u >> 9) & 3, s_rel = u >> 11;
        const int n0 = 16*s_rel + 2*q + 8*half;
        const float v0 = tr[n0*260 + h*64 + c];
        const float v1 = tr[(n0+1)*260 + h*64 + c];
        dst[(h*4 + sb + s_rel)*544 + q*136 + c*2 + half] = pack_h2(v0, v1);
    }
}

// ------- Kernel B: f16 mma, 2 row-blocks/warp, prebuilt bitmasks -------
__global__ __launch_bounds__(512, 1) void gat_mma_kernel()
{
    extern __shared__ char sm[];
    const uint32_t smb = smem_u32(sm);
    const int t = threadIdx.x;
    const int w = t >> 5, lane = t & 31;     // 16 warps
    const int h = w & 3, o4 = w >> 2;        // head, i-quarter (32 rows)
    const int rL = lane >> 2, q = lane & 3;

    const int cta = blockIdx.x;
    const int split = cta & 3, ib = cta >> 2;
    const int b = ib >> 4, i0 = (ib & 15) * MI;
    const int jbase = split * JR;

    u64 eaP[2][2];
#pragma unroll
    for (int rb = 0; rb < 2; ++rb)
#pragma unroll
        for (int rh = 0; rh < 2; ++rh) {
            const float2 e = g_sE[((size_t)b*Nn + i0 + o4*32 + rb*16 + rL + 8*rh)*Hh + h];
            asm("mov.b64 %0, {%1, %2};" : "=l"(eaP[rb][rh]) : "f"(e.x), "f"(e.y));
        }

    float acc[2][8][4], accl[2][4];
#pragma unroll
    for (int rb = 0; rb < 2; ++rb) {
#pragma unroll
        for (int n = 0; n < 8; ++n)
#pragma unroll
            for (int u = 0; u < 4; ++u) acc[rb][n][u] = 0.f;
#pragma unroll
        for (int u = 0; u < 4; ++u) accl[rb][u] = 0.f;
    }

    auto stage = [&](int tt, int st) {
        const int jt = split*8 + tt;
        const int j0 = jbase + tt*64;
        const char* srcB = (const char*)(g_hB + (size_t)(b*32 + jt)*8704);
#pragma unroll
        for (int k = 0; k < 4; ++k)
            cp16(smb + KB_B(st) + (t + k*512)*16, srcB + (size_t)(t + k*512)*16);
        if (t < 128)
            cp16(smb + KB_B(st) + (t + 2048)*16, srcB + (size_t)(t + 2048)*16);
        else if (t < 256)
            cp16(smb + KB_E(st) + (t - 128)*16,
                 (const char*)(g_dE + ((size_t)b*Nn + j0)*Hh) + (t - 128)*16);
        else if (t < 320)
            cp16(smb + KB_M(st) + (t - 256)*16,
                 (const char*)(g_mask + (size_t)(b*32 + jt)*Nn + i0) + (t - 256)*16);
        CP_COMMIT();
    };

    stage(0, 0);
    for (int tt = 0; tt < NT; ++tt) {
        const int st = tt & 1;
        if (tt + 1 < NT) { stage(tt + 1, st ^ 1); CP_WAIT(1); }
        else             { CP_WAIT(0); }
        __syncthreads();

        const unsigned* sB = (const unsigned*)(sm + KB_B(st));
        const float2*  sE  = (const float2*)(sm + KB_E(st));
        const uint2*   sM  = (const uint2*)(sm + KB_M(st));

        uint2 mA[2], mC[2];
#pragma unroll
        for (int rb = 0; rb < 2; ++rb) {
            mA[rb] = sM[o4*32 + rb*16 + rL];
            mC[rb] = sM[o4*32 + rb*16 + rL + 8];
        }

#pragma unroll
        for (int s = 0; s < 4; ++s) {
            const int jb = 16*s + 2*q;
            const u64 e0 = *(const u64*)&sE[jb*4 + h];
            const u64 e1 = *(const u64*)&sE[(jb+1)*4 + h];
            const u64 e8 = *(const u64*)&sE[(jb+8)*4 + h];
            const u64 e9 = *(const u64*)&sE[(jb+9)*4 + h];
            uint2 bv[8];
            const uint2* bp = (const uint2*)sB + ((h*4 + s)*544 + q*136)/2;
#pragma unroll
            for (int n = 0; n < 8; ++n) bv[n] = bp[8*n + rL];

            const int sh = 8*s + q;
#pragma unroll
            for (int rb = 0; rb < 2; ++rb) {
                const unsigned ax = mA[rb].x >> sh, ay = mA[rb].y >> sh;
                const unsigned cx = mC[rb].x >> sh, cy = mC[rb].y >> sh;
                const float p00 = (ax & 1u)  ? pmax2p(eaP[rb][0], e0) : 0.f;
                const float p01 = (ay & 1u)  ? pmax2p(eaP[rb][0], e1) : 0.f;
                const float p08 = (ax & 16u) ? pmax2p(eaP[rb][0], e8) : 0.f;
                const float p09 = (ay & 16u) ? pmax2p(eaP[rb][0], e9) : 0.f;
                const float p10 = (cx & 1u)  ? pmax2p(eaP[rb][1], e0) : 0.f;
                const float p11 = (cy & 1u)  ? pmax2p(eaP[rb][1], e1) : 0.f;
                const float p18 = (cx & 16u) ? pmax2p(eaP[rb][1], e8) : 0.f;
                const float p19 = (cy & 16u) ? pmax2p(eaP[rb][1], e9) : 0.f;
                const unsigned f0 = pack_h2(p00, p01);
                const unsigned f1 = pack_h2(p10, p11);
                const unsigned f2 = pack_h2(p08, p09);
                const unsigned f3 = pack_h2(p18, p19);
#pragma unroll
                for (int n = 0; n < 8; ++n)
                    mma_f16(acc[rb][n], f0, f1, f2, f3, bv[n].x, bv[n].y);
                mma_f16(accl[rb], f0, f1, f2, f3, ONES_H2, ONES_H2);
            }
        }
        __syncthreads();
    }

    if (q == 0) {
#pragma unroll
        for (int rb = 0; rb < 2; ++rb) {
            const int r0 = o4*32 + rb*16 + rL;
            g_lsum[((size_t)cta*MI + r0)*Hh + h]     = accl[rb][0];
            g_lsum[((size_t)cta*MI + r0 + 8)*Hh + h] = accl[rb][2];
        }
    }
    float* gp = g_part + (size_t)cta*MI*HC;
#pragma unroll
    for (int rb = 0; rb < 2; ++rb) {
        const int r0 = o4*32 + rb*16 + rL;
#pragma unroll
        for (int n = 0; n < 8; ++n) {
            const int ch = h*64 + 8*n + 2*q;
            *(float2*)(gp + (size_t)r0*HC + ch)     = make_float2(acc[rb][n][0], acc[rb][n][1]);
            *(float2*)(gp + (size_t)(r0+8)*HC + ch) = make_float2(acc[rb][n][2], acc[rb][n][3]);
        }
    }
}

// ---------------- Kernel C (unchanged) ----------------
__global__ __launch_bounds__(256) void merge_kernel(
    const float* __restrict__ bgat, const float* __restrict__ gamma,
    const float* __restrict__ beta, float* __restrict__ out)
{
    const int t = threadIdx.x, w = t >> 5, lane = t & 31;
    const int row = blockIdx.x*8 + w;
    const int ib = row >> 7, il = row & 127, hd = lane >> 3;

    float4 n0 = {0,0,0,0}, n1 = {0,0,0,0};
    float ls = 0.f;
#pragma unroll
    for (int s = 0; s < SPLIT; ++s) {
        const int cta = ib*SPLIT + s;
        const float4* p = (const float4*)(g_part + ((size_t)cta*MI + il)*HC + lane*8);
        const float4 x = p[0], y = p[1];
        n0.x += x.x; n0.y += x.y; n0.z += x.z; n0.w += x.w;
        n1.x += y.x; n1.y += y.y; n1.z += y.z; n1.w += y.w;
        ls += g_lsum[((size_t)cta*MI + il)*Hh + hd];
    }
    const float inv = __fdividef(1.f, ls);
    const int ch = lane*8;
    const float4 bgA = *(const float4*)(bgat + ch), bgB = *(const float4*)(bgat + ch + 4);
    float v[8];
    v[0]=fmaf(n0.x,inv,bgA.x); v[1]=fmaf(n0.y,inv,bgA.y);
    v[2]=fmaf(n0.z,inv,bgA.z); v[3]=fmaf(n0.w,inv,bgA.w);
    v[4]=fmaf(n1.x,inv,bgB.x); v[5]=fmaf(n1.y,inv,bgB.y);
    v[6]=fmaf(n1.z,inv,bgB.z); v[7]=fmaf(n1.w,inv,bgB.w);
    float s1 = 0.f, s2 = 0.f;
#pragma unroll
    for (int k = 0; k < 8; ++k) {
        float x = v[k];
        x = x > 0.f ? x : expm1f(x);
        v[k] = x; s1 += x; s2 = fmaf(x, x, s2);
    }
#pragma unroll
    for (int o = 16; o; o >>= 1) {
        s1 += __shfl_xor_sync(0xffffffffu, s1, o);
        s2 += __shfl_xor_sync(0xffffffffu, s2, o);
    }
    const float mu = s1 * (1.f/HC);
    const float var = fmaf(-mu, mu, s2 * (1.f/HC));
    const float rstd = rsqrtf(var + 1e-3f);
    const float4 gaA = *(const float4*)(gamma + ch), gaB = *(const float4*)(gamma + ch + 4);
    const float4 btA = *(const float4*)(beta + ch),  btB = *(const float4*)(beta + ch + 4);
    float4 o1, o2;
    o1.x=fmaf((v[0]-mu)*rstd,gaA.x,btA.x); o1.y=fmaf((v[1]-mu)*rstd,gaA.y,btA.y);
    o1.z=fmaf((v[2]-mu)*rstd,gaA.z,btA.z); o1.w=fmaf((v[3]-mu)*rstd,gaA.w,btA.w);
    o2.x=fmaf((v[4]-mu)*rstd,gaB.x,btB.x); o2.y=fmaf((v[5]-mu)*rstd,gaB.y,btB.y);
    o2.z=fmaf((v[6]-mu)*rstd,gaB.z,btB.z); o2.w=fmaf((v[7]-mu)*rstd,gaB.w,btB.w);
    *(float4*)(out + (size_t)row*HC + ch)     = o1;
    *(float4*)(out + (size_t)row*HC + ch + 4) = o2;
}

extern "C" void kernel_launch(void* const* d_in, const int* in_sizes, int n_in,
                              void* d_out, int out_size)
{
    (void)in_sizes; (void)n_in; (void)out_size;
    const float* X     = (const float*)d_in[0];
    const float* A     = (const float*)d_in[1];
    // E/W_edge/b_edge dead: sigmoid>0 => A*gate==0 <=> A==0
    const float* W_gat = (const float*)d_in[5];
    const float* a_src = (const float*)d_in[6];
    const float* a_dst = (const float*)d_in[7];
    const float* b_gat = (const float*)d_in[8];
    const float* gamma = (const float*)d_in[9];
    const float* beta  = (const float*)d_in[10];
    float* out = (float*)d_out;

    cudaFuncSetAttribute(precompute_kernel, cudaFuncAttributeMaxDynamicSharedMemorySize, SMP_TOT);
    cudaFuncSetAttribute(gat_mma_kernel, cudaFuncAttributeMaxDynamicSharedMemorySize, KB_TOT);

    precompute_kernel<<<GEMM_BLKS + MASK_BLKS, 512, SMP_TOT>>>(X, W_gat, a_src, a_dst, A);
    gat_mma_kernel<<<NCTA, 512, KB_TOT>>>();
    merge_kernel<<<(Bb*Nn)/8, 256>>>(b_gat, gamma, beta, out);
}

// round 15
// speedup vs baseline: 1.7475x; 1.7475x over previous
#include <cuda_runtime.h>
#include <cstdint>

#define Bb 2
#define Nn 2048
#define Ff 128
#define Hh 4
#define HC 256
#define MI 128
#define SPLIT 4
#define JR (Nn/SPLIT)
#define NT (JR/64)
#define NCTA ((Bb*Nn/MI)*SPLIT)  // 128

// kernel-B smem: double-buffered {B-image 34816, eb 2048} + 2x1024B masks
#define KB_STG   36864
#define KB_B(st) ((st)*KB_STG)
#define KB_E(st) (34816 + (st)*KB_STG)
#define KB_M(st) (73728 + (st)*1024)
#define KB_TOT   75776

// precompute smem (32 nodes/CTA) — identical to round 13
#define SMP_XS     0
#define SMP_WS(st) (16384 + (st)*32768)
#define SMP_RS     81920
#define SMP_RD     82432
#define SMP_TOT    82944
#define SMP_TR     16384

typedef unsigned long long u64;

__device__ unsigned g_hB [Bb*32*8704];     // f16x2 fragment image per 64-j tile
__device__ float2   g_sE [Bb*Nn*Hh];
__device__ float2   g_dE [Bb*Nn*Hh];
__device__ float    g_part[(size_t)NCTA*MI*HC];
__device__ float    g_lsum[NCTA*MI*Hh];

#define ONES_H2 0x3C003C00u

__device__ __forceinline__ unsigned pack_h2(float lo, float hi) {
    unsigned r; asm("cvt.rn.f16x2.f32 %0, %1, %2;" : "=r"(r) : "f"(hi), "f"(lo));
    return r;
}
__device__ __forceinline__ void mma_f16(float* d, unsigned a0, unsigned a1,
                                        unsigned a2, unsigned a3, unsigned b0, unsigned b1) {
    asm volatile("mma.sync.aligned.m16n8k16.row.col.f32.f16.f16.f32 "
        "{%0,%1,%2,%3}, {%4,%5,%6,%7}, {%8,%9}, {%0,%1,%2,%3};"
        : "+f"(d[0]), "+f"(d[1]), "+f"(d[2]), "+f"(d[3])
        : "r"(a0), "r"(a1), "r"(a2), "r"(a3), "r"(b0), "r"(b1));
}
__device__ __forceinline__ float pmax2p(u64 a, u64 b) {
    u64 dv; float lo, hi;
    asm("mul.rn.f32x2 %0, %1, %2;" : "=l"(dv) : "l"(a), "l"(b));
    asm("mov.b64 {%0, %1}, %2;" : "=f"(lo), "=f"(hi) : "l"(dv));
    return fmaxf(lo, hi);
}
__device__ __forceinline__ uint32_t smem_u32(const void* p) {
    uint32_t a;
    asm("{ .reg .u64 t; cvta.to.shared.u64 t, %1; cvt.u32.u64 %0, t; }" : "=r"(a) : "l"(p));
    return a;
}
__device__ __forceinline__ void cp16(uint32_t dst, const void* src) {
    asm volatile("cp.async.cg.shared.global [%0], [%1], 16;" :: "r"(dst), "l"(src));
}
#define CP_COMMIT() asm volatile("cp.async.commit_group;" ::: "memory")
#define CP_WAIT(n)  asm volatile("cp.async.wait_group %0;" :: "n"(n) : "memory")

// ---------------- Kernel A (identical to round 13, passing, 14.0us) ----------------
__global__ __launch_bounds__(512) void precompute_kernel(
    const float* __restrict__ X, const float* __restrict__ Wg,
    const float* __restrict__ asrc, const float* __restrict__ adst)
{
    extern __shared__ char smp[];
    float* xs    = (float*)(smp + SMP_XS);
    float* red_s = (float*)(smp + SMP_RS);
    float* red_d = (float*)(smp + SMP_RD);
    const int t   = threadIdx.x;
    const int bn0 = blockIdx.x * 32;
    const int c4  = t & 63, nq = t >> 6;
    const uint32_t smb = smem_u32(smp);

#pragma unroll
    for (int r = 0; r < 2; ++r) {
        const int u = t + r*512, n = u >> 5, f4 = u & 31;
        *(float4*)&xs[n*Ff + f4*4] = *(const float4*)(X + (size_t)(bn0+n)*Ff + f4*4);
    }
    auto stageW = [&](int fc, int st) {
#pragma unroll
        for (int k = 0; k < 4; ++k) {
            const int u = t + k*512, lf = u >> 6, cq = u & 63;
            cp16(smb + SMP_WS(st) + (lf*256 + cq*4)*4,
                 Wg + (size_t)(cq>>4)*(Ff*64) + (size_t)(fc+lf)*64 + (cq&15)*4);
        }
        CP_COMMIT();
    };

    float acc[4][4];
#pragma unroll
    for (int jj = 0; jj < 4; ++jj)
#pragma unroll
        for (int cc = 0; cc < 4; ++cc) acc[jj][cc] = 0.f;

    stageW(0, 0);
    for (int ch = 0; ch < 4; ++ch) {
        const int st = ch & 1;
        if (ch + 1 < 4) { stageW(32*(ch+1), st ^ 1); CP_WAIT(1); }
        else            { CP_WAIT(0); }
        __syncthreads();
        const float* ws = (const float*)(smp + SMP_WS(st));
#pragma unroll
        for (int lf = 0; lf < 32; ++lf) {
            const float4 w4 = *(const float4*)&ws[lf*256 + 4*c4];
            const float x0 = xs[(4*nq+0)*Ff + 32*ch + lf];
            const float x1 = xs[(4*nq+1)*Ff + 32*ch + lf];
            const float x2 = xs[(4*nq+2)*Ff + 32*ch + lf];
            const float x3 = xs[(4*nq+3)*Ff + 32*ch + lf];
            acc[0][0]=fmaf(x0,w4.x,acc[0][0]); acc[0][1]=fmaf(x0,w4.y,acc[0][1]);
            acc[0][2]=fmaf(x0,w4.z,acc[0][2]); acc[0][3]=fmaf(x0,w4.w,acc[0][3]);
            acc[1][0]=fmaf(x1,w4.x,acc[1][0]); acc[1][1]=fmaf(x1,w4.y,acc[1][1]);
            acc[1][2]=fmaf(x1,w4.z,acc[1][2]); acc[1][3]=fmaf(x1,w4.w,acc[1][3]);
            acc[2][0]=fmaf(x2,w4.x,acc[2][0]); acc[2][1]=fmaf(x2,w4.y,acc[2][1]);
            acc[2][2]=fmaf(x2,w4.z,acc[2][2]); acc[2][3]=fmaf(x2,w4.w,acc[2][3]);
            acc[3][0]=fmaf(x3,w4.x,acc[3][0]); acc[3][1]=fmaf(x3,w4.y,acc[3][1]);
            acc[3][2]=fmaf(x3,w4.z,acc[3][2]); acc[3][3]=fmaf(x3,w4.w,acc[3][3]);
        }
        __syncthreads();
    }

    const float4 as4 = *(const float4*)(asrc + 4*c4);
    const float4 ad4 = *(const float4*)(adst + 4*c4);
#pragma unroll
    for (int jj = 0; jj < 4; ++jj) {
        float ps = acc[jj][0]*as4.x + acc[jj][1]*as4.y + acc[jj][2]*as4.z + acc[jj][3]*as4.w;
        float pd = acc[jj][0]*ad4.x + acc[jj][1]*ad4.y + acc[jj][2]*ad4.z + acc[jj][3]*ad4.w;
#pragma unroll
        for (int o = 1; o < 16; o <<= 1) {
            ps += __shfl_xor_sync(0xffffffffu, ps, o);
            pd += __shfl_xor_sync(0xffffffffu, pd, o);
        }
        if ((t & 15) == 0) {
            red_s[(4*nq+jj)*4 + (c4>>4)] = ps;
            red_d[(4*nq+jj)*4 + (c4>>4)] = pd;
        }
    }
    __syncthreads();

    float* tr = (float*)(smp + SMP_TR);
#pragma unroll
    for (int jj = 0; jj < 4; ++jj)
        *(float4*)&tr[(4*nq+jj)*260 + 4*c4] =
            make_float4(acc[jj][0], acc[jj][1], acc[jj][2], acc[jj][3]);
    if (t < 128) {
        const int n = t >> 2, h = t & 3;
        const float ss = red_s[n*4 + h], sd = red_d[n*4 + h];
        g_sE[(size_t)(bn0+n)*Hh + h] = make_float2(__expf(ss), __expf(0.2f*ss));
        g_dE[(size_t)(bn0+n)*Hh + h] = make_float2(__expf(sd), __expf(0.2f*sd));
    }
    __syncthreads();

    const int b = bn0 >> 11, nl = bn0 & (Nn-1);
    const int T = nl >> 6, sb = (nl & 63) >> 4;
    unsigned* dst = g_hB + (size_t)(b*32 + T)*8704;
#pragma unroll
    for (int k = 0; k < 8; ++k) {
        const int u = t + k*512;
        const int half = u & 1, c = (u >> 1) & 63;
        const int q = (u >> 7) & 3, h = (u >> 9) & 3, s_rel = u >> 11;
        const int n0 = 16*s_rel + 2*q + 8*half;
        const float v0 = tr[n0*260 + h*64 + c];
        const float v1 = tr[(n0+1)*260 + h*64 + c];
        dst[(h*4 + sb + s_rel)*544 + q*136 + c*2 + half] = pack_h2(v0, v1);
    }
}

// ---- Kernel B: 512 thr, 2 row-blocks/warp, in-kernel ballot masks (1-reg encode) ----
__global__ __launch_bounds__(512, 1) void gat_mma_kernel(const float* __restrict__ A)
{
    extern __shared__ char sm[];
    const uint32_t smb = smem_u32(sm);
    const int t = threadIdx.x;
    const int w = t >> 5, lane = t & 31;     // 16 warps
    const int h = w & 3, o4 = w >> 2;        // head, i-quarter (32 rows)
    const int rL = lane >> 2, q = lane & 3;

    const int cta = blockIdx.x;
    const int split = cta & 3, ib = cta >> 2;
    const int b = ib >> 4, i0 = (ib & 15) * MI;
    const int jbase = split * JR;

    u64 eaP[2][2];
#pragma unroll
    for (int rb = 0; rb < 2; ++rb)
#pragma unroll
        for (int rh = 0; rh < 2; ++rh) {
            const float2 e = g_sE[((size_t)b*Nn + i0 + o4*32 + rb*16 + rL + 8*rh)*Hh + h];
            asm("mov.b64 %0, {%1, %2};" : "=l"(eaP[rb][rh]) : "f"(e.x), "f"(e.y));
        }

    float acc[2][8][4], accl[2][4];
#pragma unroll
    for (int rb = 0; rb < 2; ++rb) {
#pragma unroll
        for (int n = 0; n < 8; ++n)
#pragma unroll
            for (int u = 0; u < 4; ++u) acc[rb][n][u] = 0.f;
#pragma unroll
        for (int u = 0; u < 4; ++u) accl[rb][u] = 0.f;
    }

    // A prefetch -> 16 nonzero-bits in ONE register (16 elements/thread = 128x64 tile)
    unsigned avbits = 0;
    auto loadA = [&](int tt) {
        const int j0 = jbase + tt*64;
        unsigned bits = 0;
#pragma unroll
        for (int k = 0; k < 16; ++k) {
            const int u = t + k*512;
            const float v = __ldcs(A + ((size_t)b*Nn + i0 + (u>>6))*Nn + j0 + (u&63));
            bits |= (v != 0.f ? 1u : 0u) << k;
        }
        avbits = bits;
    };
    // masks: uint2 per row = (ballot of j0..31, ballot of j32..63)
    auto ballot_store = [&](int mb) {
#pragma unroll
        for (int k = 0; k < 16; ++k) {
            const unsigned bw = __ballot_sync(0xffffffffu, (avbits >> k) & 1u);
            if (lane == 0)
                *(unsigned*)(sm + KB_M(mb) + (((unsigned)(t + k*512)) >> 5)*4) = bw;
        }
    };
    auto stage = [&](int tt, int st) {
        const int j0 = jbase + tt*64;
        const char* srcB = (const char*)(g_hB + (size_t)(b*32 + split*8 + tt)*8704);
#pragma unroll
        for (int k = 0; k < 4; ++k)
            cp16(smb + KB_B(st) + (t + k*512)*16, srcB + (size_t)(t + k*512)*16);
        if (t < 128)
            cp16(smb + KB_B(st) + (t + 2048)*16, srcB + (size_t)(t + 2048)*16);
        else if (t < 256)
            cp16(smb + KB_E(st) + (t - 128)*16,
                 (const char*)(g_dE + ((size_t)b*Nn + j0)*Hh) + (t - 128)*16);
        CP_COMMIT();
    };

    loadA(0);
    stage(0, 0);
    ballot_store(0);
    loadA(1);

    for (int tt = 0; tt < NT; ++tt) {
        const int st = tt & 1;
        if (tt + 1 < NT) { stage(tt + 1, st ^ 1); CP_WAIT(1); }
        else             { CP_WAIT(0); }
        __syncthreads();

        const unsigned* sB = (const unsigned*)(sm + KB_B(st));
        const float2*  sE  = (const float2*)(sm + KB_E(st));
        const uint2*   sM  = (const uint2*)(sm + KB_M(st));

        uint2 mA[2], mC[2];
#pragma unroll
        for (int rb = 0; rb < 2; ++rb) {
            mA[rb] = sM[o4*32 + rb*16 + rL];
            mC[rb] = sM[o4*32 + rb*16 + rL + 8];
        }

#pragma unroll
        for (int s = 0; s < 4; ++s) {
            const int jb = 16*s + 2*q;
            const u64 e0 = *(const u64*)&sE[jb*4 + h];
            const u64 e1 = *(const u64*)&sE[(jb+1)*4 + h];
            const u64 e8 = *(const u64*)&sE[(jb+8)*4 + h];
            const u64 e9 = *(const u64*)&sE[(jb+9)*4 + h];
            uint2 bv[8];
            const uint2* bp = (const uint2*)sB + ((h*4 + s)*544 + q*136)/2;
#pragma unroll
            for (int n = 0; n < 8; ++n) bv[n] = bp[8*n + rL];

            const int sh = (s & 1)*16 + 2*q;
#pragma unroll
            for (int rb = 0; rb < 2; ++rb) {
                const unsigned w0 = ((s < 2) ? mA[rb].x : mA[rb].y) >> sh;
                const unsigned w1 = ((s < 2) ? mC[rb].x : mC[rb].y) >> sh;
                const float p00 = (w0 & 1u)   ? pmax2p(eaP[rb][0], e0) : 0.f;
                const float p01 = (w0 & 2u)   ? pmax2p(eaP[rb][0], e1) : 0.f;
                const float p08 = (w0 & 256u) ? pmax2p(eaP[rb][0], e8) : 0.f;
                const float p09 = (w0 & 512u) ? pmax2p(eaP[rb][0], e9) : 0.f;
                const float p10 = (w1 & 1u)   ? pmax2p(eaP[rb][1], e0) : 0.f;
                const float p11 = (w1 & 2u)   ? pmax2p(eaP[rb][1], e1) : 0.f;
                const float p18 = (w1 & 256u) ? pmax2p(eaP[rb][1], e8) : 0.f;
                const float p19 = (w1 & 512u) ? pmax2p(eaP[rb][1], e9) : 0.f;
                const unsigned f0 = pack_h2(p00, p01);
                const unsigned f1 = pack_h2(p10, p11);
                const unsigned f2 = pack_h2(p08, p09);
                const unsigned f3 = pack_h2(p18, p19);
#pragma unroll
                for (int n = 0; n < 8; ++n)
                    mma_f16(acc[rb][n], f0, f1, f2, f3, bv[n].x, bv[n].y);
                mma_f16(accl[rb], f0, f1, f2, f3, ONES_H2, ONES_H2);
            }
        }

        // masks for tile tt+1 into the other buffer (its readers finished
        // before this tile's first barrier), then prefetch A(tt+2)
        if (tt + 1 < NT) {
            ballot_store(st ^ 1);
            if (tt + 2 < NT) loadA(tt + 2);
        }
        __syncthreads();
    }

    if (q == 0) {
#pragma unroll
        for (int rb = 0; rb < 2; ++rb) {
            const int r0 = o4*32 + rb*16 + rL;
            g_lsum[((size_t)cta*MI + r0)*Hh + h]     = accl[rb][0];
            g_lsum[((size_t)cta*MI + r0 + 8)*Hh + h] = accl[rb][2];
        }
    }
    float* gp = g_part + (size_t)cta*MI*HC;
#pragma unroll
    for (int rb = 0; rb < 2; ++rb) {
        const int r0 = o4*32 + rb*16 + rL;
#pragma unroll
        for (int n = 0; n < 8; ++n) {
            const int ch = h*64 + 8*n + 2*q;
            *(float2*)(gp + (size_t)r0*HC + ch)     = make_float2(acc[rb][n][0], acc[rb][n][1]);
            *(float2*)(gp + (size_t)(r0+8)*HC + ch) = make_float2(acc[rb][n][2], acc[rb][n][3]);
        }
    }
}

// ---------------- Kernel C (unchanged) ----------------
__global__ __launch_bounds__(256) void merge_kernel(
    const float* __restrict__ bgat, const float* __restrict__ gamma,
    const float* __restrict__ beta, float* __restrict__ out)
{
    const int t = threadIdx.x, w = t >> 5, lane = t & 31;
    const int row = blockIdx.x*8 + w;
    const int ib = row >> 7, il = row & 127, hd = lane >> 3;

    float4 n0 = {0,0,0,0}, n1 = {0,0,0,0};
    float ls = 0.f;
#pragma unroll
    for (int s = 0; s < SPLIT; ++s) {
        const int cta = ib*SPLIT + s;
        const float4* p = (const float4*)(g_part + ((size_t)cta*MI + il)*HC + lane*8);
        const float4 x = p[0], y = p[1];
        n0.x += x.x; n0.y += x.y; n0.z += x.z; n0.w += x.w;
        n1.x += y.x; n1.y += y.y; n1.z += y.z; n1.w += y.w;
        ls += g_lsum[((size_t)cta*MI + il)*Hh + hd];
    }
    const float inv = __fdividef(1.f, ls);
    const int ch = lane*8;
    const float4 bgA = *(const float4*)(bgat + ch), bgB = *(const float4*)(bgat + ch + 4);
    float v[8];
    v[0]=fmaf(n0.x,inv,bgA.x); v[1]=fmaf(n0.y,inv,bgA.y);
    v[2]=fmaf(n0.z,inv,bgA.z); v[3]=fmaf(n0.w,inv,bgA.w);
    v[4]=fmaf(n1.x,inv,bgB.x); v[5]=fmaf(n1.y,inv,bgB.y);
    v[6]=fmaf(n1.z,inv,bgB.z); v[7]=fmaf(n1.w,inv,bgB.w);
    float s1 = 0.f, s2 = 0.f;
#pragma unroll
    for (int k = 0; k < 8; ++k) {
        float x = v[k];
        x = x > 0.f ? x : expm1f(x);
        v[k] = x; s1 += x; s2 = fmaf(x, x, s2);
    }
#pragma unroll
    for (int o = 16; o; o >>= 1) {
        s1 += __shfl_xor_sync(0xffffffffu, s1, o);
        s2 += __shfl_xor_sync(0xffffffffu, s2, o);
    }
    const float mu = s1 * (1.f/HC);
    const float var = fmaf(-mu, mu, s2 * (1.f/HC));
    const float rstd = rsqrtf(var + 1e-3f);
    const float4 gaA = *(const float4*)(gamma + ch), gaB = *(const float4*)(gamma + ch + 4);
    const float4 btA = *(const float4*)(beta + ch),  btB = *(const float4*)(beta + ch + 4);
    float4 o1, o2;
    o1.x=fmaf((v[0]-mu)*rstd,gaA.x,btA.x); o1.y=fmaf((v[1]-mu)*rstd,gaA.y,btA.y);
    o1.z=fmaf((v[2]-mu)*rstd,gaA.z,btA.z); o1.w=fmaf((v[3]-mu)*rstd,gaA.w,btA.w);
    o2.x=fmaf((v[4]-mu)*rstd,gaB.x,btB.x); o2.y=fmaf((v[5]-mu)*rstd,gaB.y,btB.y);
    o2.z=fmaf((v[6]-mu)*rstd,gaB.z,btB.z); o2.w=fmaf((v[7]-mu)*rstd,gaB.w,btB.w);
    *(float4*)(out + (size_t)row*HC + ch)     = o1;
    *(float4*)(out + (size_t)row*HC + ch + 4) = o2;
}

extern "C" void kernel_launch(void* const* d_in, const int* in_sizes, int n_in,
                              void* d_out, int out_size)
{
    (void)in_sizes; (void)n_in; (void)out_size;
    const float* X     = (const float*)d_in[0];
    const float* A     = (const float*)d_in[1];
    // E/W_edge/b_edge dead: sigmoid>0 => A*gate==0 <=> A==0
    const float* W_gat = (const float*)d_in[5];
    const float* a_src = (const float*)d_in[6];
    const float* a_dst = (const float*)d_in[7];
    const float* b_gat = (const float*)d_in[8];
    const float* gamma = (const float*)d_in[9];
    const float* beta  = (const float*)d_in[10];
    float* out = (float*)d_out;

    cudaFuncSetAttribute(precompute_kernel, cudaFuncAttributeMaxDynamicSharedMemorySize, SMP_TOT);
    cudaFuncSetAttribute(gat_mma_kernel, cudaFuncAttributeMaxDynamicSharedMemorySize, KB_TOT);

    precompute_kernel<<<(Bb*Nn)/32, 512, SMP_TOT>>>(X, W_gat, a_src, a_dst);
    gat_mma_kernel<<<NCTA, 512, KB_TOT>>>(A);
    merge_kernel<<<(Bb*Nn)/8, 256>>>(b_gat, gamma, beta, out);
}

// round 16
// speedup vs baseline: 2.0383x; 1.1664x over previous
#include <cuda_runtime.h>
#include <cstdint>

#define Bb 2
#define Nn 2048
#define Ff 128
#define Hh 4
#define HC 256
#define MI 128
#define SPLIT 4
#define JR (Nn/SPLIT)
#define NT (JR/64)
#define NCTA ((Bb*Nn/MI)*SPLIT)  // 128

// kernel-B smem: double-buffered {B-image 34816, eb 2048} + persistent masks 8192
#define KB_STG   36864
#define KB_B(st) ((st)*KB_STG)
#define KB_E(st) (34816 + (st)*KB_STG)
#define KB_MK    73728
#define KB_TOT   81920

// precompute smem (32 nodes/CTA) — identical to round 13
#define SMP_XS     0
#define SMP_WS(st) (16384 + (st)*32768)
#define SMP_RS     81920
#define SMP_RD     82432
#define SMP_TOT    82944
#define SMP_TR     16384

typedef unsigned long long u64;

__device__ unsigned g_hB [Bb*32*8704];     // f16x2 fragment image per 64-j tile
__device__ float2   g_sE [Bb*Nn*Hh];
__device__ float2   g_dE [Bb*Nn*Hh];
__device__ float    g_part[(size_t)NCTA*MI*HC];
__device__ float    g_lsum[NCTA*MI*Hh];

#define ONES_H2 0x3C003C00u

__device__ __forceinline__ unsigned pack_h2(float lo, float hi) {
    unsigned r; asm("cvt.rn.f16x2.f32 %0, %1, %2;" : "=r"(r) : "f"(hi), "f"(lo));
    return r;
}
__device__ __forceinline__ void mma_f16(float* d, unsigned a0, unsigned a1,
                                        unsigned a2, unsigned a3, unsigned b0, unsigned b1) {
    asm volatile("mma.sync.aligned.m16n8k16.row.col.f32.f16.f16.f32 "
        "{%0,%1,%2,%3}, {%4,%5,%6,%7}, {%8,%9}, {%0,%1,%2,%3};"
        : "+f"(d[0]), "+f"(d[1]), "+f"(d[2]), "+f"(d[3])
        : "r"(a0), "r"(a1), "r"(a2), "r"(a3), "r"(b0), "r"(b1));
}
__device__ __forceinline__ float pmax2p(u64 a, u64 b) {
    u64 dv; float lo, hi;
    asm("mul.rn.f32x2 %0, %1, %2;" : "=l"(dv) : "l"(a), "l"(b));
    asm("mov.b64 {%0, %1}, %2;" : "=f"(lo), "=f"(hi) : "l"(dv));
    return fmaxf(lo, hi);
}
__device__ __forceinline__ uint32_t smem_u32(const void* p) {
    uint32_t a;
    asm("{ .reg .u64 t; cvta.to.shared.u64 t, %1; cvt.u32.u64 %0, t; }" : "=r"(a) : "l"(p));
    return a;
}
__device__ __forceinline__ void cp16(uint32_t dst, const void* src) {
    asm volatile("cp.async.cg.shared.global [%0], [%1], 16;" :: "r"(dst), "l"(src));
}
#define CP_COMMIT() asm volatile("cp.async.commit_group;" ::: "memory")
#define CP_WAIT(n)  asm volatile("cp.async.wait_group %0;" :: "n"(n) : "memory")

// ---------------- Kernel A (identical to round 13, passing, 14.0us) ----------------
__global__ __launch_bounds__(512) void precompute_kernel(
    const float* __restrict__ X, const float* __restrict__ Wg,
    const float* __restrict__ asrc, const float* __restrict__ adst)
{
    extern __shared__ char smp[];
    float* xs    = (float*)(smp + SMP_XS);
    float* red_s = (float*)(smp + SMP_RS);
    float* red_d = (float*)(smp + SMP_RD);
    const int t   = threadIdx.x;
    const int bn0 = blockIdx.x * 32;
    const int c4  = t & 63, nq = t >> 6;
    const uint32_t smb = smem_u32(smp);

#pragma unroll
    for (int r = 0; r < 2; ++r) {
        const int u = t + r*512, n = u >> 5, f4 = u & 31;
        *(float4*)&xs[n*Ff + f4*4] = *(const float4*)(X + (size_t)(bn0+n)*Ff + f4*4);
    }
    auto stageW = [&](int fc, int st) {
#pragma unroll
        for (int k = 0; k < 4; ++k) {
            const int u = t + k*512, lf = u >> 6, cq = u & 63;
            cp16(smb + SMP_WS(st) + (lf*256 + cq*4)*4,
                 Wg + (size_t)(cq>>4)*(Ff*64) + (size_t)(fc+lf)*64 + (cq&15)*4);
        }
        CP_COMMIT();
    };

    float acc[4][4];
#pragma unroll
    for (int jj = 0; jj < 4; ++jj)
#pragma unroll
        for (int cc = 0; cc < 4; ++cc) acc[jj][cc] = 0.f;

    stageW(0, 0);
    for (int ch = 0; ch < 4; ++ch) {
        const int st = ch & 1;
        if (ch + 1 < 4) { stageW(32*(ch+1), st ^ 1); CP_WAIT(1); }
        else            { CP_WAIT(0); }
        __syncthreads();
        const float* ws = (const float*)(smp + SMP_WS(st));
#pragma unroll
        for (int lf = 0; lf < 32; ++lf) {
            const float4 w4 = *(const float4*)&ws[lf*256 + 4*c4];
            const float x0 = xs[(4*nq+0)*Ff + 32*ch + lf];
            const float x1 = xs[(4*nq+1)*Ff + 32*ch + lf];
            const float x2 = xs[(4*nq+2)*Ff + 32*ch + lf];
            const float x3 = xs[(4*nq+3)*Ff + 32*ch + lf];
            acc[0][0]=fmaf(x0,w4.x,acc[0][0]); acc[0][1]=fmaf(x0,w4.y,acc[0][1]);
            acc[0][2]=fmaf(x0,w4.z,acc[0][2]); acc[0][3]=fmaf(x0,w4.w,acc[0][3]);
            acc[1][0]=fmaf(x1,w4.x,acc[1][0]); acc[1][1]=fmaf(x1,w4.y,acc[1][1]);
            acc[1][2]=fmaf(x1,w4.z,acc[1][2]); acc[1][3]=fmaf(x1,w4.w,acc[1][3]);
            acc[2][0]=fmaf(x2,w4.x,acc[2][0]); acc[2][1]=fmaf(x2,w4.y,acc[2][1]);
            acc[2][2]=fmaf(x2,w4.z,acc[2][2]); acc[2][3]=fmaf(x2,w4.w,acc[2][3]);
            acc[3][0]=fmaf(x3,w4.x,acc[3][0]); acc[3][1]=fmaf(x3,w4.y,acc[3][1]);
            acc[3][2]=fmaf(x3,w4.z,acc[3][2]); acc[3][3]=fmaf(x3,w4.w,acc[3][3]);
        }
        __syncthreads();
    }

    const float4 as4 = *(const float4*)(asrc + 4*c4);
    const float4 ad4 = *(const float4*)(adst + 4*c4);
#pragma unroll
    for (int jj = 0; jj < 4; ++jj) {
        float ps = acc[jj][0]*as4.x + acc[jj][1]*as4.y + acc[jj][2]*as4.z + acc[jj][3]*as4.w;
        float pd = acc[jj][0]*ad4.x + acc[jj][1]*ad4.y + acc[jj][2]*ad4.z + acc[jj][3]*ad4.w;
#pragma unroll
        for (int o = 1; o < 16; o <<= 1) {
            ps += __shfl_xor_sync(0xffffffffu, ps, o);
            pd += __shfl_xor_sync(0xffffffffu, pd, o);
        }
        if ((t & 15) == 0) {
            red_s[(4*nq+jj)*4 + (c4>>4)] = ps;
            red_d[(4*nq+jj)*4 + (c4>>4)] = pd;
        }
    }
    __syncthreads();

    float* tr = (float*)(smp + SMP_TR);
#pragma unroll
    for (int jj = 0; jj < 4; ++jj)
        *(float4*)&tr[(4*nq+jj)*260 + 4*c4] =
            make_float4(acc[jj][0], acc[jj][1], acc[jj][2], acc[jj][3]);
    if (t < 128) {
        const int n = t >> 2, h = t & 3;
        const float ss = red_s[n*4 + h], sd = red_d[n*4 + h];
        g_sE[(size_t)(bn0+n)*Hh + h] = make_float2(__expf(ss), __expf(0.2f*ss));
        g_dE[(size_t)(bn0+n)*Hh + h] = make_float2(__expf(sd), __expf(0.2f*sd));
    }
    __syncthreads();

    const int b = bn0 >> 11, nl = bn0 & (Nn-1);
    const int T = nl >> 6, sb = (nl & 63) >> 4;
    unsigned* dst = g_hB + (size_t)(b*32 + T)*8704;
#pragma unroll
    for (int k = 0; k < 8; ++k) {
        const int u = t + k*512;
        const int half = u & 1, c = (u >> 1) & 63;
        const int q = (u >> 7) & 3, h = (u >> 9) & 3, s_rel = u >> 11;
        const int n0 = 16*s_rel + 2*q + 8*half;
        const float v0 = tr[n0*260 + h*64 + c];
        const float v1 = tr[(n0+1)*260 + h*64 + c];
        dst[(h*4 + sb + s_rel)*544 + q*136 + c*2 + half] = pack_h2(v0, v1);
    }
}

// ---- Kernel B: masks built once in prologue (persistent smem), f16 mma loop ----
__global__ __launch_bounds__(512, 1) void gat_mma_kernel(const float* __restrict__ A)
{
    extern __shared__ char sm[];
    const uint32_t smb = smem_u32(sm);
    const int t = threadIdx.x;
    const int w = t >> 5, lane = t & 31;     // 16 warps
    const int h = w & 3, o4 = w >> 2;        // head, i-quarter (32 rows)
    const int rL = lane >> 2, q = lane & 3;

    const int cta = blockIdx.x;
    const int split = cta & 3, ib = cta >> 2;
    const int b = ib >> 4, i0 = (ib & 15) * MI;
    const int jbase = split * JR;

    u64 eaP[2][2];
#pragma unroll
    for (int rb = 0; rb < 2; ++rb)
#pragma unroll
        for (int rh = 0; rh < 2; ++rh) {
            const float2 e = g_sE[((size_t)b*Nn + i0 + o4*32 + rb*16 + rL + 8*rh)*Hh + h];
            asm("mov.b64 %0, {%1, %2};" : "=l"(eaP[rb][rh]) : "f"(e.x), "f"(e.y));
        }

    float acc[2][8][4], accl[2][4];
#pragma unroll
    for (int rb = 0; rb < 2; ++rb) {
#pragma unroll
        for (int n = 0; n < 8; ++n)
#pragma unroll
            for (int u = 0; u < 4; ++u) acc[rb][n][u] = 0.f;
#pragma unroll
        for (int u = 0; u < 4; ++u) accl[rb][u] = 0.f;
    }

    auto stage = [&](int tt, int st) {
        const int j0 = jbase + tt*64;
        const char* srcB = (const char*)(g_hB + (size_t)(b*32 + split*8 + tt)*8704);
#pragma unroll
        for (int k = 0; k < 4; ++k)
            cp16(smb + KB_B(st) + (t + k*512)*16, srcB + (size_t)(t + k*512)*16);
        if (t < 128)
            cp16(smb + KB_B(st) + (t + 2048)*16, srcB + (size_t)(t + 2048)*16);
        else if (t < 256)
            cp16(smb + KB_E(st) + (t - 128)*16,
                 (const char*)(g_dE + ((size_t)b*Nn + j0)*Hh) + (t - 128)*16);
        CP_COMMIT();
    };

    // prologue: kick off tile-0 staging, then build this CTA's masks
    // (128 rows x 8 tiles, uint2 per (tile,row)) from A with batch-8 MLP.
    stage(0, 0);
    {
        const int wj = w * 64;                 // 64 jobs/warp; job = (row, tile)
        for (int bt = 0; bt < 8; ++bt) {
            float2 f[8];
#pragma unroll
            for (int k = 0; k < 8; ++k) {
                const int jid = wj + bt*8 + k;
                const int row = jid & 127, tl = jid >> 7;
                f[k] = __ldcs((const float2*)(A + ((size_t)b*Nn + i0 + row)*Nn
                                              + jbase + tl*64 + lane*2));
            }
#pragma unroll
            for (int k = 0; k < 8; ++k) {
                const int jid = wj + bt*8 + k;
                const int row = jid & 127, tl = jid >> 7;
                const unsigned bx = __ballot_sync(0xffffffffu, f[k].x != 0.f);
                const unsigned by = __ballot_sync(0xffffffffu, f[k].y != 0.f);
                if (lane == 0)
                    *(uint2*)(sm + KB_MK + (tl*128 + row)*8) = make_uint2(bx, by);
            }
        }
    }

    for (int tt = 0; tt < NT; ++tt) {
        const int st = tt & 1;
        if (tt + 1 < NT) { stage(tt + 1, st ^ 1); CP_WAIT(1); }
        else             { CP_WAIT(0); }
        __syncthreads();   // first one also publishes the masks

        const unsigned* sB = (const unsigned*)(sm + KB_B(st));
        const float2*  sE  = (const float2*)(sm + KB_E(st));
        const uint2*   sMK = (const uint2*)(sm + KB_MK + tt*1024);

        uint2 mA[2], mC[2];
#pragma unroll
        for (int rb = 0; rb < 2; ++rb) {
            mA[rb] = sMK[o4*32 + rb*16 + rL];
            mC[rb] = sMK[o4*32 + rb*16 + rL + 8];
        }

#pragma unroll
        for (int s = 0; s < 4; ++s) {
            const int jb = 16*s + 2*q;
            const u64 e0 = *(const u64*)&sE[jb*4 + h];
            const u64 e1 = *(const u64*)&sE[(jb+1)*4 + h];
            const u64 e8 = *(const u64*)&sE[(jb+8)*4 + h];
            const u64 e9 = *(const u64*)&sE[(jb+9)*4 + h];
            uint2 bv[8];
            const uint2* bp = (const uint2*)sB + ((h*4 + s)*544 + q*136)/2;
#pragma unroll
            for (int n = 0; n < 8; ++n) bv[n] = bp[8*n + rL];

            const int sh = 8*s + q;            // x-bit k <-> j=2k ; y-bit k <-> j=2k+1
#pragma unroll
            for (int rb = 0; rb < 2; ++rb) {
                const unsigned ax = mA[rb].x >> sh, ay = mA[rb].y >> sh;
                const unsigned cx = mC[rb].x >> sh, cy = mC[rb].y >> sh;
                const float p00 = (ax & 1u)  ? pmax2p(eaP[rb][0], e0) : 0.f;
                const float p01 = (ay & 1u)  ? pmax2p(eaP[rb][0], e1) : 0.f;
                const float p08 = (ax & 16u) ? pmax2p(eaP[rb][0], e8) : 0.f;
                const float p09 = (ay & 16u) ? pmax2p(eaP[rb][0], e9) : 0.f;
                const float p10 = (cx & 1u)  ? pmax2p(eaP[rb][1], e0) : 0.f;
                const float p11 = (cy & 1u)  ? pmax2p(eaP[rb][1], e1) : 0.f;
                const float p18 = (cx & 16u) ? pmax2p(eaP[rb][1], e8) : 0.f;
                const float p19 = (cy & 16u) ? pmax2p(eaP[rb][1], e9) : 0.f;
                const unsigned f0 = pack_h2(p00, p01);
                const unsigned f1 = pack_h2(p10, p11);
                const unsigned f2 = pack_h2(p08, p09);
                const unsigned f3 = pack_h2(p18, p19);
#pragma unroll
                for (int n = 0; n < 8; ++n)
                    mma_f16(acc[rb][n], f0, f1, f2, f3, bv[n].x, bv[n].y);
                mma_f16(accl[rb], f0, f1, f2, f3, ONES_H2, ONES_H2);
            }
        }
        __syncthreads();
    }

    if (q == 0) {
#pragma unroll
        for (int rb = 0; rb < 2; ++rb) {
            const int r0 = o4*32 + rb*16 + rL;
            g_lsum[((size_t)cta*MI + r0)*Hh + h]     = accl[rb][0];
            g_lsum[((size_t)cta*MI + r0 + 8)*Hh + h] = accl[rb][2];
        }
    }
    float* gp = g_part + (size_t)cta*MI*HC;
#pragma unroll
    for (int rb = 0; rb < 2; ++rb) {
        const int r0 = o4*32 + rb*16 + rL;
#pragma unroll
        for (int n = 0; n < 8; ++n) {
            const int ch = h*64 + 8*n + 2*q;
            *(float2*)(gp + (size_t)r0*HC + ch)     = make_float2(acc[rb][n][0], acc[rb][n][1]);
            *(float2*)(gp + (size_t)(r0+8)*HC + ch) = make_float2(acc[rb][n][2], acc[rb][n][3]);
        }
    }
}

// ---------------- Kernel C (unchanged) ----------------
__global__ __launch_bounds__(256) void merge_kernel(
    const float* __restrict__ bgat, const float* __restrict__ gamma,
    const float* __restrict__ beta, float* __restrict__ out)
{
    const int t = threadIdx.x, w = t >> 5, lane = t & 31;
    const int row = blockIdx.x*8 + w;
    const int ib = row >> 7, il = row & 127, hd = lane >> 3;

    float4 n0 = {0,0,0,0}, n1 = {0,0,0,0};
    float ls = 0.f;
#pragma unroll
    for (int s = 0; s < SPLIT; ++s) {
        const int cta = ib*SPLIT + s;
        const float4* p = (const float4*)(g_part + ((size_t)cta*MI + il)*HC + lane*8);
        const float4 x = p[0], y = p[1];
        n0.x += x.x; n0.y += x.y; n0.z += x.z; n0.w += x.w;
        n1.x += y.x; n1.y += y.y; n1.z += y.z; n1.w += y.w;
        ls += g_lsum[((size_t)cta*MI + il)*Hh + hd];
    }
    const float inv = __fdividef(1.f, ls);
    const int ch = lane*8;
    const float4 bgA = *(const float4*)(bgat + ch), bgB = *(const float4*)(bgat + ch + 4);
    float v[8];
    v[0]=fmaf(n0.x,inv,bgA.x); v[1]=fmaf(n0.y,inv,bgA.y);
    v[2]=fmaf(n0.z,inv,bgA.z); v[3]=fmaf(n0.w,inv,bgA.w);
    v[4]=fmaf(n1.x,inv,bgB.x); v[5]=fmaf(n1.y,inv,bgB.y);
    v[6]=fmaf(n1.z,inv,bgB.z); v[7]=fmaf(n1.w,inv,bgB.w);
    float s1 = 0.f, s2 = 0.f;
#pragma unroll
    for (int k = 0; k < 8; ++k) {
        float x = v[k];
        x = x > 0.f ? x : expm1f(x);
        v[k] = x; s1 += x; s2 = fmaf(x, x, s2);
    }
#pragma unroll
    for (int o = 16; o; o >>= 1) {
        s1 += __shfl_xor_sync(0xffffffffu, s1, o);
        s2 += __shfl_xor_sync(0xffffffffu, s2, o);
    }
    const float mu = s1 * (1.f/HC);
    const float var = fmaf(-mu, mu, s2 * (1.f/HC));
    const float rstd = rsqrtf(var + 1e-3f);
    const float4 gaA = *(const float4*)(gamma + ch), gaB = *(const float4*)(gamma + ch + 4);
    const float4 btA = *(const float4*)(beta + ch),  btB = *(const float4*)(beta + ch + 4);
    float4 o1, o2;
    o1.x=fmaf((v[0]-mu)*rstd,gaA.x,btA.x); o1.y=fmaf((v[1]-mu)*rstd,gaA.y,btA.y);
    o1.z=fmaf((v[2]-mu)*rstd,gaA.z,btA.z); o1.w=fmaf((v[3]-mu)*rstd,gaA.w,btA.w);
    o2.x=fmaf((v[4]-mu)*rstd,gaB.x,btB.x); o2.y=fmaf((v[5]-mu)*rstd,gaB.y,btB.y);
    o2.z=fmaf((v[6]-mu)*rstd,gaB.z,btB.z); o2.w=fmaf((v[7]-mu)*rstd,gaB.w,btB.w);
    *(float4*)(out + (size_t)row*HC + ch)     = o1;
    *(float4*)(out + (size_t)row*HC + ch + 4) = o2;
}

extern "C" void kernel_launch(void* const* d_in, const int* in_sizes, int n_in,
                              void* d_out, int out_size)
{
    (void)in_sizes; (void)n_in; (void)out_size;
    const float* X     = (const float*)d_in[0];
    const float* A     = (const float*)d_in[1];
    // E/W_edge/b_edge dead: sigmoid>0 => A*gate==0 <=> A==0
    const float* W_gat = (const float*)d_in[5];
    const float* a_src = (const float*)d_in[6];
    const float* a_dst = (const float*)d_in[7];
    const float* b_gat = (const float*)d_in[8];
    const float* gamma = (const float*)d_in[9];
    const float* beta  = (const float*)d_in[10];
    float* out = (float*)d_out;

    cudaFuncSetAttribute(precompute_kernel, cudaFuncAttributeMaxDynamicSharedMemorySize, SMP_TOT);
    cudaFuncSetAttribute(gat_mma_kernel, cudaFuncAttributeMaxDynamicSharedMemorySize, KB_TOT);

    precompute_kernel<<<(Bb*Nn)/32, 512, SMP_TOT>>>(X, W_gat, a_src, a_dst);
    gat_mma_kernel<<<NCTA, 512, KB_TOT>>>(A);
    merge_kernel<<<(Bb*Nn)/8, 256>>>(b_gat, gamma, beta, out);
}